// round 6
// baseline (speedup 1.0000x reference)
#include <cuda_runtime.h>
#include <cstddef>

// Problem constants (match reference_code)
#define NU 500000
#define NP 100000
#define DIMF 64
#define UF (NU * DIMF)   // 32,000,000 floats (128 MB)
#define PF (NP * DIMF)   //  6,400,000 floats (25.6 MB)

// ---------------------------------------------------------------------------
// Scratch (static device globals — allocation-guard-safe). ~461 MB total.
// Each layer's output lives in its own buffer; final mean reads all three.
// ---------------------------------------------------------------------------
__device__ float g_au0[UF];
__device__ float g_au1[UF];
__device__ float g_au2[UF];
__device__ float g_ap0[PF];
__device__ float g_ap1[PF];
__device__ float g_ap2[PF];

__device__ int   g_deg_er[NU];
__device__ int   g_deg_ew[NU];
__device__ int   g_deg_rr[NP];
__device__ int   g_deg_rw[NP];
__device__ float g_scl_er[NU];
__device__ float g_scl_ew[NU];
__device__ float g_scl_rr[NP];
__device__ float g_scl_rw[NP];

// ---------------------------------------------------------------------------
// Vector f32 L2 reduction with scalar fallback (keeps the kernel benchable
// even if the toolchain rejects the v4 form).
// ---------------------------------------------------------------------------
__device__ __forceinline__ void red_add_v4(float* dst, float a, float b, float c, float d) {
#if defined(__CUDA_ARCH__) && (__CUDA_ARCH__ >= 900)
    asm volatile("red.global.add.v4.f32 [%0], {%1,%2,%3,%4};"
                 :: "l"(dst), "f"(a), "f"(b), "f"(c), "f"(d) : "memory");
#else
    atomicAdd(dst + 0, a); atomicAdd(dst + 1, b);
    atomicAdd(dst + 2, c); atomicAdd(dst + 3, d);
#endif
}

// ---------------------------------------------------------------------------
// Kernels
// ---------------------------------------------------------------------------
__global__ void k_zero_f4(float4* __restrict__ p, int n4) {
    int i = blockIdx.x * blockDim.x + threadIdx.x;
    if (i < n4) p[i] = make_float4(0.f, 0.f, 0.f, 0.f);
}

__global__ void k_zero_deg(int* __restrict__ du0, int* __restrict__ du1,
                           int* __restrict__ dp0, int* __restrict__ dp1) {
    int i = blockIdx.x * blockDim.x + threadIdx.x;
    if (i < NU) { du0[i] = 0; du1[i] = 0; }
    if (i < NP) { dp0[i] = 0; dp1[i] = 0; }
}

// All four degree histograms in one launch (4 independent edge lists).
__global__ void k_deg4(const int* __restrict__ er, const int* __restrict__ ew,
                       const int* __restrict__ rr, const int* __restrict__ rw, int E,
                       int* __restrict__ der, int* __restrict__ dew,
                       int* __restrict__ drr, int* __restrict__ drw) {
    int i = blockIdx.x * blockDim.x + threadIdx.x;
    if (i >= E) return;
    atomicAdd(&der[er[i]], 1);
    atomicAdd(&dew[ew[i]], 1);
    atomicAdd(&drr[rr[i]], 1);
    atomicAdd(&drw[rw[i]], 1);
}

// scale = 0.5 / max(deg, 1): folds degree-normalization AND the (r+w)/2 avg.
__global__ void k_scale2(const int* __restrict__ da, float* __restrict__ sa,
                         const int* __restrict__ db, float* __restrict__ sb, int n) {
    int i = blockIdx.x * blockDim.x + threadIdx.x;
    if (i < n) {
        int a = da[i], b = db[i];
        sa[i] = 0.5f / (float)(a > 1 ? a : 1);
        sb[i] = 0.5f / (float)(b > 1 ? b : 1);
    }
}

// Fused dual-edge-list scatter:  agg[src] += scale[src] * feat[dst]
// for both edge lists of one phase. 16 threads per edge, one float4 each.
// Grid-stride over 2*E*16 work items (32-bit: 40M < 2^31). E is a multiple
// of 16, so the list boundary is warp-aligned -> no intra-warp divergence.
__global__ void __launch_bounds__(256, 8)
k_scatter2(const int* __restrict__ e1, const float* __restrict__ scl1,
           const int* __restrict__ e2, const float* __restrict__ scl2,
           int E,
           const float* __restrict__ feat,
           float* __restrict__ agg) {
    const int half  = E * 16;
    const int total = half * 2;
    const int step  = gridDim.x * blockDim.x;
    for (int t = blockIdx.x * blockDim.x + threadIdx.x; t < total; t += step) {
        const int* edges; const float* scale; int w = t;
        if (w < half) { edges = e1; scale = scl1; }
        else          { edges = e2; scale = scl2; w -= half; }
        int e    = w >> 4;
        int lane = w & 15;
        int s = __ldg(edges + e);          // broadcast within the 16-lane group
        int d = __ldg(edges + E + e);
        float4 v = __ldg(reinterpret_cast<const float4*>(feat) + ((size_t)d << 4) + lane);
        float sc = __ldg(scale + s);
        float* dst = agg + ((size_t)s << 6) + (lane << 2);
        red_add_v4(dst, v.x * sc, v.y * sc, v.z * sc, v.w * sc);
    }
}

// out = 0.25 * (base + l1 + l2 + l3)   (mean over the 4 layer snapshots)
__global__ void k_final3(const float4* __restrict__ base,
                         const float4* __restrict__ a,
                         const float4* __restrict__ b,
                         const float4* __restrict__ c,
                         float4* __restrict__ out, int n4) {
    int i = blockIdx.x * blockDim.x + threadIdx.x;
    if (i < n4) {
        float4 x = base[i], p = a[i], q = b[i], r = c[i];
        x.x = 0.25f * (x.x + p.x + q.x + r.x);
        x.y = 0.25f * (x.y + p.y + q.y + r.y);
        x.z = 0.25f * (x.z + p.z + q.z + r.z);
        x.w = 0.25f * (x.w + p.w + q.w + r.w);
        out[i] = x;
    }
}

// ---------------------------------------------------------------------------
// Launch (no statics, no caching — harness contract)
// ---------------------------------------------------------------------------
static inline int nblk(long long n, int t) { return (int)((n + t - 1) / t); }

extern "C" void kernel_launch(void* const* d_in, const int* in_sizes, int n_in,
                              void* d_out, int out_size) {
    const float* user_emb  = (const float*)d_in[0];
    const float* paper_emb = (const float*)d_in[1];
    const int*   er        = (const int*)d_in[2];
    const int*   ew        = (const int*)d_in[3];
    const int*   rr        = (const int*)d_in[4];
    const int*   rw        = (const int*)d_in[5];
    const int E = in_sizes[2] / 2;

    float* out = (float*)d_out;

    float *au[3], *ap[3];
    float *scl_er, *scl_ew, *scl_rr, *scl_rw;
    int *deg_er, *deg_ew, *deg_rr, *deg_rw;
    cudaGetSymbolAddress((void**)&au[0], g_au0);
    cudaGetSymbolAddress((void**)&au[1], g_au1);
    cudaGetSymbolAddress((void**)&au[2], g_au2);
    cudaGetSymbolAddress((void**)&ap[0], g_ap0);
    cudaGetSymbolAddress((void**)&ap[1], g_ap1);
    cudaGetSymbolAddress((void**)&ap[2], g_ap2);
    cudaGetSymbolAddress((void**)&deg_er, g_deg_er);
    cudaGetSymbolAddress((void**)&deg_ew, g_deg_ew);
    cudaGetSymbolAddress((void**)&deg_rr, g_deg_rr);
    cudaGetSymbolAddress((void**)&deg_rw, g_deg_rw);
    cudaGetSymbolAddress((void**)&scl_er, g_scl_er);
    cudaGetSymbolAddress((void**)&scl_ew, g_scl_ew);
    cudaGetSymbolAddress((void**)&scl_rr, g_scl_rr);
    cudaGetSymbolAddress((void**)&scl_rw, g_scl_rw);

    const int T = 256;
    const int UF4 = UF / 4, PF4 = PF / 4;

    // 1) degrees -> scales (layer-invariant, computed once per replay)
    k_zero_deg<<<nblk(NU, T), T>>>(deg_er, deg_ew, deg_rr, deg_rw);
    k_deg4<<<nblk(E, T), T>>>(er, ew, rr, rw, E, deg_er, deg_ew, deg_rr, deg_rw);
    k_scale2<<<nblk(NU, T), T>>>(deg_er, scl_er, deg_ew, scl_ew, NU);
    k_scale2<<<nblk(NP, T), T>>>(deg_rr, scl_rr, deg_rw, scl_rw, NP);

    // 2) zero all six layer-output accumulators upfront
    for (int L = 0; L < 3; L++) {
        k_zero_f4<<<nblk(UF4, T), T>>>((float4*)au[L], UF4);
        k_zero_f4<<<nblk(PF4, T), T>>>((float4*)ap[L], PF4);
    }

    // 3) layers: each phase is ONE fused dual-list scatter
    const long long ST2 = (long long)E * 32;   // both lists, 16 threads/edge
    const int sgrid = nblk(ST2, T);
    for (int L = 0; L < 3; L++) {
        const float* xp_src = (L == 0) ? paper_emb : ap[L - 1];
        // user update: au[L] = 0.5*(er_agg/deg + ew_agg/deg)
        k_scatter2<<<sgrid, T>>>(er, scl_er, ew, scl_ew, E, xp_src, au[L]);
        // paper update gathers the NEW user embeddings au[L]
        k_scatter2<<<sgrid, T>>>(rr, scl_rr, rw, scl_rw, E, au[L], ap[L]);
    }

    // 4) finalize: mean over {layer-0 emb, L1, L2, L3}; out = [u_final | p_final]
    k_final3<<<nblk(UF4, T), T>>>((const float4*)user_emb,
                                  (const float4*)au[0], (const float4*)au[1],
                                  (const float4*)au[2], (float4*)out, UF4);
    k_final3<<<nblk(PF4, T), T>>>((const float4*)paper_emb,
                                  (const float4*)ap[0], (const float4*)ap[1],
                                  (const float4*)ap[2],
                                  (float4*)(out + (size_t)UF), PF4);
}